// round 4
// baseline (speedup 1.0000x reference)
#include <cuda_runtime.h>

#define HDIM 512
#define BATCH 256
#define TLEN 512
#define NSTEPS 511          // steps use trg[:, 0..510]
#define FC1_N 1024
#define FC2_N 32000

#define NCTA 128
#define CTA_THREADS 512
#define KCOLS 16            // k-columns per CTA (8 k-pairs)
#define BTILE 64            // batch rows per CTA

// dynamic smem: W slice [512][64] floats + h chunk [32][64] u64 (duplicated)
#define SW_FLOATS (HDIM * 64)
#define SMEM_BYTES (SW_FLOATS * 4 + 32 * 64 * 8)

// -------- persistent device scratch (no allocations allowed) --------
__device__ float g_ht[2][HDIM * BATCH];   // hidden transposed [k][b], dbl-buffered
__device__ float g_hlast[BATCH * HDIM];   // final hidden, [b][k]
__device__ float g_z[BATCH * FC1_N];      // fc1 output
__device__ unsigned int g_arrive;         // grid barrier arrival counter
__device__ unsigned int g_gen;            // grid barrier generation

// -------- packed fp32x2 helpers --------
__device__ __forceinline__ unsigned long long pack2(float lo, float hi) {
    unsigned long long r;
    asm("mov.b64 %0, {%1, %2};" : "=l"(r) : "f"(lo), "f"(hi));
    return r;
}
__device__ __forceinline__ void unpack2(unsigned long long v, float& lo, float& hi) {
    asm("mov.b64 {%0, %1}, %2;" : "=f"(lo), "=f"(hi) : "l"(v));
}
__device__ __forceinline__ void ffma2(unsigned long long& d,
                                      unsigned long long a, unsigned long long b) {
    asm("fma.rn.f32x2 %0, %1, %2, %0;" : "+l"(d) : "l"(a), "l"(b));
}
__device__ __forceinline__ unsigned int ld_acq(const unsigned int* p) {
    unsigned int v;
    asm volatile("ld.global.acquire.gpu.b32 %0, [%1];" : "=r"(v) : "l"(p));
    return v;
}
__device__ __forceinline__ float sigmoidf_(float x) {
    return 1.0f / (1.0f + expf(-x));
}
__device__ __forceinline__ float tanhf_(float x) {
    return 1.0f - 2.0f / (expf(2.0f * x) + 1.0f);
}

// -------- init: zero ht[0], reset barrier --------
__global__ void zero_state() {
    int i = blockIdx.x * blockDim.x + threadIdx.x;
    int stride = gridDim.x * blockDim.x;
    for (int j = i; j < HDIM * BATCH; j += stride) g_ht[0][j] = 0.0f;
    if (i == 0) { g_arrive = 0u; g_gen = 0u; }
}

// ============================================================================
// Persistent LSTM: all 511 timesteps in one kernel.
// Grid 128 CTAs (32 k-tiles x 4 b-tiles), 512 threads, 1 CTA/SM.
// CTA tile: 64 batch x 16 k-cols (x4 gates), FULL K=512 (no split-K).
// W slice (64 gate-cols x 512 K = 131kB) persists in SMEM for all steps,
// layout [kk][cc][g] packed as f32x2 so 4 gate weights = 2x LDS.128.
// Thread: 1 batch x 2 k x 4 gates (4 f32x2 accs); c held in registers.
// Steps separated by an in-kernel grid barrier; h exchanged via g_ht (L2,
// __ldcg/__stcg to bypass non-coherent L1).
// ============================================================================
__global__ __launch_bounds__(CTA_THREADS, 1)
void lstm_persistent(const int* __restrict__ trg,
                     const float* __restrict__ w_hh,   // (2048, 512) row-major
                     const float* __restrict__ w_ih,   // (2048, 1)
                     const float* __restrict__ b_ih,   // (2048,)
                     const float* __restrict__ b_hh)   // (2048,)
{
    extern __shared__ unsigned char dynsmem[];
    float* sW = (float*)dynsmem;                                  // [512][64]
    unsigned long long* sH = (unsigned long long*)(dynsmem + SW_FLOATS * 4); // [32][64]
    const unsigned long long* sWu = (const unsigned long long*)sW;

    const int t   = threadIdx.x;
    const int bid = blockIdx.x;
    const int kx  = bid & 31;          // 32 k-tiles
    const int by  = bid >> 5;          // 4 b-tiles
    const int k0  = kx * KCOLS;
    const int b0  = by * BTILE;

    const int cc = t & 7;              // k-pair 0..7
    const int bl = t >> 3;             // batch lane 0..63
    const int b  = b0 + bl;

    // ---- preload W slice into smem, layout float[kk][cc*8 + g*2 + half] ----
    {
        const int col = t & 63;        // 0..63 -> gate g, col j within tile
        const int g   = col >> 4;
        const int j   = col & 15;
        const int ks  = (t >> 6) * 64; // kk slice 0..448
        const float* src = w_hh + (size_t)(g * HDIM + k0 + j) * HDIM + ks;
        const int fcol = (j >> 1) * 8 + g * 2 + (j & 1);
#pragma unroll
        for (int q = 0; q < 64; q += 4) {
            float4 v = *(const float4*)(src + q);
            sW[(ks + q + 0) * 64 + fcol] = v.x;
            sW[(ks + q + 1) * 64 + fcol] = v.y;
            sW[(ks + q + 2) * 64 + fcol] = v.z;
            sW[(ks + q + 3) * 64 + fcol] = v.w;
        }
    }

    // ---- per-thread constants: bias + w_ih for 4 gates x 2 k ----
    float bias_lo[4], bias_hi[4], wih_lo[4], wih_hi[4];
#pragma unroll
    for (int g = 0; g < 4; g++) {
        int r = g * HDIM + k0 + 2 * cc;
        float2 bi2 = *(const float2*)(b_ih + r);
        float2 bh2 = *(const float2*)(b_hh + r);
        float2 wi2 = *(const float2*)(w_ih + r);
        bias_lo[g] = bi2.x + bh2.x;  bias_hi[g] = bi2.y + bh2.y;
        wih_lo[g]  = wi2.x;          wih_hi[g]  = wi2.y;
    }

    float c_lo = 0.0f, c_hi = 0.0f;    // cell state lives in registers

    // h-chunk staging map: thread loads 4 floats of ht row (kc+skk)
    const int skk = t >> 4;            // 0..31
    const int sbq = t & 15;            // 0..15 -> floats sbq*4..+3

    __syncthreads();                   // W resident

#pragma unroll 1
    for (int s = 0; s < NSTEPS; s++) {
        const float* __restrict__ ht_in  = g_ht[s & 1];
        float*       __restrict__ ht_out = g_ht[(s & 1) ^ 1];

        const float x = (float)__ldg(&trg[b * TLEN + s]);
        unsigned long long acc[4];
#pragma unroll
        for (int g = 0; g < 4; g++)
            acc[g] = pack2(fmaf(x, wih_lo[g], bias_lo[g]),
                           fmaf(x, wih_hi[g], bias_hi[g]));

#pragma unroll 1
        for (int kc = 0; kc < HDIM; kc += 32) {
            // stage h chunk (duplicated f32x2), bypass L1 (cross-SM producer)
            float4 hv = __ldcg((const float4*)(ht_in + (size_t)(kc + skk) * BATCH
                                               + b0 + sbq * 4));
            sH[skk * 64 + sbq * 4 + 0] = pack2(hv.x, hv.x);
            sH[skk * 64 + sbq * 4 + 1] = pack2(hv.y, hv.y);
            sH[skk * 64 + sbq * 4 + 2] = pack2(hv.z, hv.z);
            sH[skk * 64 + sbq * 4 + 3] = pack2(hv.w, hv.w);
            __syncthreads();

#pragma unroll
            for (int kk = 0; kk < 32; kk++) {
                unsigned long long h2 = sH[kk * 64 + bl];
                const unsigned long long* wr = sWu + (size_t)(kc + kk) * 32 + cc * 4;
                ulonglong2 wa = *(const ulonglong2*)(wr);      // gates 0,1
                ulonglong2 wb = *(const ulonglong2*)(wr + 2);  // gates 2,3
                ffma2(acc[0], wa.x, h2);
                ffma2(acc[1], wa.y, h2);
                ffma2(acc[2], wb.x, h2);
                ffma2(acc[3], wb.y, h2);
            }
            __syncthreads();
        }

        // ---- pointwise LSTM update (gate order i, f, g, o) ----
        float iv0, iv1, fv0, fv1, gv0, gv1, ov0, ov1;
        unpack2(acc[0], iv0, iv1);
        unpack2(acc[1], fv0, fv1);
        unpack2(acc[2], gv0, gv1);
        unpack2(acc[3], ov0, ov1);

        float i0 = sigmoidf_(iv0), f0 = sigmoidf_(fv0), gg0 = tanhf_(gv0), o0 = sigmoidf_(ov0);
        float i1 = sigmoidf_(iv1), f1 = sigmoidf_(fv1), gg1 = tanhf_(gv1), o1 = sigmoidf_(ov1);
        c_lo = fmaf(f0, c_lo, i0 * gg0);
        c_hi = fmaf(f1, c_hi, i1 * gg1);
        float h0 = o0 * tanhf_(c_lo);
        float h1 = o1 * tanhf_(c_hi);

        const int kcol = k0 + 2 * cc;
        __stcg(&ht_out[(size_t)kcol * BATCH + b], h0);
        __stcg(&ht_out[(size_t)(kcol + 1) * BATCH + b], h1);
        if (s == NSTEPS - 1) {
            g_hlast[(size_t)b * HDIM + kcol]     = h0;
            g_hlast[(size_t)b * HDIM + kcol + 1] = h1;
        }

        // ---- grid barrier between steps ----
        if (s < NSTEPS - 1) {
            __syncthreads();
            if (t == 0) {
                __threadfence();
                unsigned prev = atomicAdd(&g_arrive, 1u);
                if (prev == (unsigned)(NCTA - 1)) {
                    atomicExch(&g_arrive, 0u);
                    __threadfence();
                    atomicExch(&g_gen, (unsigned)(s + 1));
                } else {
                    while (ld_acq(&g_gen) < (unsigned)(s + 1)) { }
                }
            }
            __syncthreads();
        }
    }
}

// ============================================================================
// Fused GEMM head: C[M,N] = A[M,K] @ W[N,K]^T + bias, optional ReLU.
// 32(M) x 128(N) tile, 256 threads, FFMA2. asel: 0 -> A = g_hlast, 1 -> A = g_z.
// ============================================================================
__global__ __launch_bounds__(256)
void fc_gemm(int asel,
             const float* __restrict__ W,
             const float* __restrict__ bias,
             float* __restrict__ C,
             int K, int N, int do_relu)
{
    __shared__ float  sW[32 * 128];
    __shared__ float2 sH2[32 * 33];

    const float* __restrict__ A = (asel == 0) ? &g_hlast[0] : &g_z[0];

    const int t  = threadIdx.x;
    const int n0 = blockIdx.x * 128;
    const int m0 = blockIdx.y * 32;

    const int cc  = t & 15;
    const int bg  = t >> 4;
    const int bi0 = bg * 2;

    unsigned long long acc[2][4];
#pragma unroll
    for (int g = 0; g < 4; g++) {
        float2 b2 = *(const float2*)(bias + n0 + g * 32 + 2 * cc);
        acc[0][g] = pack2(b2.x, b2.y);
        acc[1][g] = pack2(b2.x, b2.y);
    }

    const int r128 = t >> 1;
    const int hf   = t & 1;
    const float4* __restrict__ Wrow = (const float4*)(W + (size_t)(n0 + r128) * K);

    const int hbi = t >> 3;
    const int hk0 = (t & 7) * 4;

    const unsigned long long* sWu = (const unsigned long long*)sW;
    const unsigned long long* sHu = (const unsigned long long*)sH2;

    for (int kc = 0; kc < K; kc += 32) {
        if (kc) __syncthreads();
#pragma unroll
        for (int q = 0; q < 4; q++) {
            float4 v = Wrow[(kc + hf * 16) / 4 + q];
            int kl = hf * 16 + q * 4;
            sW[(kl + 0) * 128 + r128] = v.x;
            sW[(kl + 1) * 128 + r128] = v.y;
            sW[(kl + 2) * 128 + r128] = v.z;
            sW[(kl + 3) * 128 + r128] = v.w;
        }
        float4 hv = *(const float4*)(A + (size_t)(m0 + hbi) * K + kc + hk0);
        sH2[(hk0 + 0) * 33 + hbi] = make_float2(hv.x, hv.x);
        sH2[(hk0 + 1) * 33 + hbi] = make_float2(hv.y, hv.y);
        sH2[(hk0 + 2) * 33 + hbi] = make_float2(hv.z, hv.z);
        sH2[(hk0 + 3) * 33 + hbi] = make_float2(hv.w, hv.w);
        __syncthreads();

#pragma unroll 8
        for (int kk = 0; kk < 32; kk++) {
            unsigned long long h0 = sHu[kk * 33 + bi0];
            unsigned long long h1 = sHu[kk * 33 + bi0 + 1];
#pragma unroll
            for (int g = 0; g < 4; g++) {
                unsigned long long w = sWu[kk * 64 + g * 16 + cc];
                ffma2(acc[0][g], w, h0);
                ffma2(acc[1][g], w, h1);
            }
        }
    }

#pragma unroll
    for (int bb = 0; bb < 2; bb++) {
        int m = m0 + bi0 + bb;
#pragma unroll
        for (int g = 0; g < 4; g++) {
            float lo, hi;
            unpack2(acc[bb][g], lo, hi);
            if (do_relu) { lo = fmaxf(lo, 0.0f); hi = fmaxf(hi, 0.0f); }
            *(float2*)(C + (size_t)m * N + n0 + g * 32 + 2 * cc) = make_float2(lo, hi);
        }
    }
}

// ============================================================================
extern "C" void kernel_launch(void* const* d_in, const int* in_sizes, int n_in,
                              void* d_out, int out_size) {
    // metadata order: x, hidden, trg, w_ih, w_hh, b_ih, b_hh, fc1_w, fc1_b, fc2_w, fc2_b
    const int*   trg   = (const int*)  d_in[2];
    const float* w_ih  = (const float*)d_in[3];
    const float* w_hh  = (const float*)d_in[4];
    const float* b_ih  = (const float*)d_in[5];
    const float* b_hh  = (const float*)d_in[6];
    const float* fc1_w = (const float*)d_in[7];
    const float* fc1_b = (const float*)d_in[8];
    const float* fc2_w = (const float*)d_in[9];
    const float* fc2_b = (const float*)d_in[10];
    float* out = (float*)d_out;

    static bool attr_set = false;
    if (!attr_set) {
        cudaFuncSetAttribute(lstm_persistent,
                             cudaFuncAttributeMaxDynamicSharedMemorySize, SMEM_BYTES);
        attr_set = true;
    }

    zero_state<<<128, 256>>>();

    lstm_persistent<<<NCTA, CTA_THREADS, SMEM_BYTES>>>(trg, w_hh, w_ih, b_ih, b_hh);

    // z = relu(h_last @ fc1_w^T + fc1_b)
    void* zptr_sym = nullptr;
    cudaGetSymbolAddress(&zptr_sym, g_z);
    float* zptr = (float*)zptr_sym;
    fc_gemm<<<dim3(FC1_N / 128, BATCH / 32), 256>>>(
        0, fc1_w, fc1_b, zptr, HDIM, FC1_N, 1);

    // out = z @ fc2_w^T + fc2_b
    fc_gemm<<<dim3(FC2_N / 128, BATCH / 32), 256>>>(
        1, fc2_w, fc2_b, out, FC1_N, FC2_N, 0);
}